// round 1
// baseline (speedup 1.0000x reference)
#include <cuda_runtime.h>
#include <math.h>

#define BATCH 512
#define TLEN  32768
#define LBLK  128
#define PBLK  (TLEN / LBLK)       // 256 blocks per row
#define NBLK  (BATCH * PBLK)      // 131072 total blocks

// ---- device-global state (no allocations allowed) ----
__device__ float d_cf[5];         // b0, b1, b2, a1, a2 (normalized by a0)
__device__ float d_M[4];          // A^L  (m00, m01, m10, m11)
__device__ float d_v[NBLK * 2];   // per-block zero-state final state
__device__ float d_s[NBLK * 2];   // per-block true entry state

// ---------------------------------------------------------------------------
// Kernel A: compute coefficients + A^L (single thread)
// ---------------------------------------------------------------------------
__global__ void dsvf_coeffs_kernel(const float* g_raw, const float* r_raw,
                                   const float* m_hp, const float* m_bp,
                                   const float* m_lp) {
    float sg = 1.0f / (1.0f + expf(-g_raw[0]));          // sigmoid
    float gg = tanf(3.14159265358979323846f * sg * 0.5f);
    float rr = log1pf(expf(r_raw[0]));                    // softplus
    float g2 = gg * gg;
    float hp = m_hp[0], bp = m_bp[0], lp = m_lp[0];

    float b0 = g2 * lp + gg * bp + hp;
    float b1 = 2.0f * g2 * lp - 2.0f * hp;
    float b2 = g2 * lp - gg * bp + hp;
    float a0 = g2 + 2.0f * rr * gg + 1.0f;
    float a1 = 2.0f * g2 - 2.0f;
    float a2 = g2 - 2.0f * rr * gg + 1.0f;

    float inv = 1.0f / a0;
    b0 *= inv; b1 *= inv; b2 *= inv; a1 *= inv; a2 *= inv;

    d_cf[0] = b0; d_cf[1] = b1; d_cf[2] = b2; d_cf[3] = a1; d_cf[4] = a2;

    // A = [[-a1, 1], [-a2, 0]];  M = A^LBLK via repeated squaring (LBLK = 2^7)
    double m00 = -(double)a1, m01 = 1.0, m10 = -(double)a2, m11 = 0.0;
    for (int i = 0; i < 7; i++) {
        double t00 = m00 * m00 + m01 * m10;
        double t01 = m00 * m01 + m01 * m11;
        double t10 = m10 * m00 + m11 * m10;
        double t11 = m10 * m01 + m11 * m11;
        m00 = t00; m01 = t01; m10 = t10; m11 = t11;
    }
    d_M[0] = (float)m00; d_M[1] = (float)m01;
    d_M[2] = (float)m10; d_M[3] = (float)m11;
}

// One biquad step (direct form II transposed), state (z1, z2) in registers.
__device__ __forceinline__ void dsvf_step(float x, float b0, float b1, float b2,
                                          float na1, float na2,
                                          float& z1, float& z2, float& y) {
    y = fmaf(b0, x, z1);
    z1 = fmaf(na1, y, fmaf(b1, x, z2));
    z2 = fmaf(na2, y, b2 * x);
}

// ---------------------------------------------------------------------------
// Kernel B: per-block zero-state recurrence -> final state v
// ---------------------------------------------------------------------------
__global__ void __launch_bounds__(256) dsvf_blockstate_kernel(const float* __restrict__ x) {
    int g = blockIdx.x * blockDim.x + threadIdx.x;   // global block id
    float b0 = d_cf[0], b1 = d_cf[1], b2 = d_cf[2];
    float na1 = -d_cf[3], na2 = -d_cf[4];

    const float4* xp = reinterpret_cast<const float4*>(x + (size_t)g * LBLK);
    float z1 = 0.0f, z2 = 0.0f, y;
#pragma unroll
    for (int k = 0; k < LBLK / 4; k++) {
        float4 v = xp[k];
        dsvf_step(v.x, b0, b1, b2, na1, na2, z1, z2, y);
        dsvf_step(v.y, b0, b1, b2, na1, na2, z1, z2, y);
        dsvf_step(v.z, b0, b1, b2, na1, na2, z1, z2, y);
        dsvf_step(v.w, b0, b1, b2, na1, na2, z1, z2, y);
    }
    d_v[2 * g] = z1;
    d_v[2 * g + 1] = z2;
}

// ---------------------------------------------------------------------------
// Kernel C: per-row sequential combine across PBLK blocks
// ---------------------------------------------------------------------------
__global__ void dsvf_scan_kernel() {
    int b = blockIdx.x * blockDim.x + threadIdx.x;
    if (b >= BATCH) return;
    float m00 = d_M[0], m01 = d_M[1], m10 = d_M[2], m11 = d_M[3];
    float s1 = 0.0f, s2 = 0.0f;
    int base = b * PBLK;
    for (int p = 0; p < PBLK; p++) {
        int idx = 2 * (base + p);
        d_s[idx] = s1;
        d_s[idx + 1] = s2;
        float v1 = d_v[idx];
        float v2 = d_v[idx + 1];
        float t1 = fmaf(m00, s1, fmaf(m01, s2, v1));
        float t2 = fmaf(m10, s1, fmaf(m11, s2, v2));
        s1 = t1; s2 = t2;
    }
}

// ---------------------------------------------------------------------------
// Kernel D: per-block recurrence from true entry state, write y
// ---------------------------------------------------------------------------
__global__ void __launch_bounds__(256) dsvf_output_kernel(const float* __restrict__ x,
                                                          float* __restrict__ out) {
    int g = blockIdx.x * blockDim.x + threadIdx.x;
    float b0 = d_cf[0], b1 = d_cf[1], b2 = d_cf[2];
    float na1 = -d_cf[3], na2 = -d_cf[4];

    float z1 = d_s[2 * g];
    float z2 = d_s[2 * g + 1];

    const float4* xp = reinterpret_cast<const float4*>(x + (size_t)g * LBLK);
    float4* yp = reinterpret_cast<float4*>(out + (size_t)g * LBLK);
#pragma unroll
    for (int k = 0; k < LBLK / 4; k++) {
        float4 v = xp[k];
        float4 o;
        dsvf_step(v.x, b0, b1, b2, na1, na2, z1, z2, o.x);
        dsvf_step(v.y, b0, b1, b2, na1, na2, z1, z2, o.y);
        dsvf_step(v.z, b0, b1, b2, na1, na2, z1, z2, o.z);
        dsvf_step(v.w, b0, b1, b2, na1, na2, z1, z2, o.w);
        yp[k] = o;
    }
}

// ---------------------------------------------------------------------------
extern "C" void kernel_launch(void* const* d_in, const int* in_sizes, int n_in,
                              void* d_out, int out_size) {
    const float* x    = (const float*)d_in[0];
    const float* g    = (const float*)d_in[1];
    const float* r    = (const float*)d_in[2];
    const float* m_hp = (const float*)d_in[3];
    const float* m_bp = (const float*)d_in[4];
    const float* m_lp = (const float*)d_in[5];
    float* out = (float*)d_out;

    dsvf_coeffs_kernel<<<1, 1>>>(g, r, m_hp, m_bp, m_lp);
    dsvf_blockstate_kernel<<<NBLK / 256, 256>>>(x);
    dsvf_scan_kernel<<<(BATCH + 255) / 256, 256>>>();
    dsvf_output_kernel<<<NBLK / 256, 256>>>(x, out);
}

// round 4
// speedup vs baseline: 5.2887x; 5.2887x over previous
#include <cuda_runtime.h>
#include <stdint.h>
#include <math.h>

#define BATCH  512
#define TLEN   32768
#define NTH    256
#define CHUNK  8192                  // samples per chunk (32 KB)
#define NCHUNK (TLEN / CHUNK)        // 4
#define LSUB   (CHUNK / NTH)         // 32 samples per thread per chunk
#define RSTR   33                    // padded smem row stride (floats)
#define BUFSZ  (NTH * RSTR)          // 8448 floats per buffer
#define SMEM_FLOATS (2 * BUFSZ + 40)
#define SMEM_BYTES  (SMEM_FLOATS * 4)

// ---- device-global parameter state ----
__device__ float d_cf[5];      // b0, b1, b2, a1, a2 (normalized)
__device__ float d_Q[6][4];    // Q[k] = (A^32)^(2^k), k=0..5 (A = per-sample state matrix)

// ---------------------------------------------------------------------------
// Kernel A: coefficients + scan matrices (single thread, double precision)
// ---------------------------------------------------------------------------
__global__ void dsvf_coeffs_kernel(const float* g_raw, const float* r_raw,
                                   const float* m_hp, const float* m_bp,
                                   const float* m_lp) {
    float sg = 1.0f / (1.0f + expf(-g_raw[0]));
    float gg = tanf(3.14159265358979323846f * sg * 0.5f);
    float rr = log1pf(expf(r_raw[0]));
    float g2 = gg * gg;
    float hp = m_hp[0], bp = m_bp[0], lp = m_lp[0];

    float b0 = g2 * lp + gg * bp + hp;
    float b1 = 2.0f * g2 * lp - 2.0f * hp;
    float b2 = g2 * lp - gg * bp + hp;
    float a0 = g2 + 2.0f * rr * gg + 1.0f;
    float a1 = 2.0f * g2 - 2.0f;
    float a2 = g2 - 2.0f * rr * gg + 1.0f;

    float inv = 1.0f / a0;
    b0 *= inv; b1 *= inv; b2 *= inv; a1 *= inv; a2 *= inv;
    d_cf[0] = b0; d_cf[1] = b1; d_cf[2] = b2; d_cf[3] = a1; d_cf[4] = a2;

    // Per-sample state matrix A = [[-a1, 1], [-a2, 0]] (state = (z1, z2))
    double m00 = -(double)a1, m01 = 1.0, m10 = -(double)a2, m11 = 0.0;
    // A^32 via 5 squarings
    for (int i = 0; i < 5; i++) {
        double t00 = m00 * m00 + m01 * m10;
        double t01 = m00 * m01 + m01 * m11;
        double t10 = m10 * m00 + m11 * m10;
        double t11 = m10 * m01 + m11 * m11;
        m00 = t00; m01 = t01; m10 = t10; m11 = t11;
    }
    d_Q[0][0] = (float)m00; d_Q[0][1] = (float)m01;
    d_Q[0][2] = (float)m10; d_Q[0][3] = (float)m11;
    for (int k = 1; k < 6; k++) {
        double t00 = m00 * m00 + m01 * m10;
        double t01 = m00 * m01 + m01 * m11;
        double t10 = m10 * m00 + m11 * m10;
        double t11 = m10 * m01 + m11 * m11;
        m00 = t00; m01 = t01; m10 = t10; m11 = t11;
        d_Q[k][0] = (float)m00; d_Q[k][1] = (float)m01;
        d_Q[k][2] = (float)m10; d_Q[k][3] = (float)m11;
    }
}

// ---------------------------------------------------------------------------
// Helpers
// ---------------------------------------------------------------------------
__device__ __forceinline__ void dsvf_step(float x, float b0, float b1, float b2,
                                          float na1, float na2,
                                          float& z1, float& z2, float& y) {
    y = fmaf(b0, x, z1);
    z1 = fmaf(na1, y, fmaf(b1, x, z2));
    z2 = fmaf(na2, y, b2 * x);
}

// async 4-byte copy gmem -> (padded) smem
__device__ __forceinline__ void cp_async4(unsigned int dst, const float* src) {
    asm volatile("cp.async.ca.shared.global [%0], [%1], 4;\n" ::
                 "r"(dst), "l"(src));
}

// issue one chunk's loads as a cp.async group
__device__ __forceinline__ void load_chunk(const float* __restrict__ g,
                                           unsigned int sbuf, int w, int l) {
#pragma unroll
    for (int i = 0; i < 32; i++) {
        int e = (w << 10) + (i << 5) + l;      // chunk-local element index
        int row = e >> 5, col = e & 31;        // row r = thread r's data
        cp_async4(sbuf + (unsigned int)(row * RSTR + col) * 4u, g + e);
    }
    asm volatile("cp.async.commit_group;\n");
}

// intra-warp inclusive scan of 2-vector state with matrix monoid
__device__ __forceinline__ void warp_scan(float& s1, float& s2,
                                          const float Q[6][4], int l) {
#pragma unroll
    for (int d = 0; d < 5; d++) {
        int o = 1 << d;
        float u1 = __shfl_up_sync(0xffffffffu, s1, o);
        float u2 = __shfl_up_sync(0xffffffffu, s2, o);
        if (l >= o) {
            s1 = fmaf(Q[d][0], u1, fmaf(Q[d][1], u2, s1));
            s2 = fmaf(Q[d][2], u1, fmaf(Q[d][3], u2, s2));
        }
    }
}

// ---------------------------------------------------------------------------
// Fused kernel: one CTA per row; chunked double-buffered smem pipeline
// ---------------------------------------------------------------------------
__global__ void __launch_bounds__(NTH)
dsvf_fused_kernel(const float* __restrict__ x, float* __restrict__ out) {
    extern __shared__ float sm[];
    float* buf0 = sm;
    float* buf1 = sm + BUFSZ;
    float* warpsum = sm + 2 * BUFSZ;       // 16 floats
    float* entry   = warpsum + 16;         // 16 floats
    float* carry   = entry + 16;           // 2 floats

    const int tid = threadIdx.x;
    const int w = tid >> 5, l = tid & 31;
    const int row_id = blockIdx.x;

    const float b0 = d_cf[0], b1 = d_cf[1], b2 = d_cf[2];
    const float na1 = -d_cf[3], na2 = -d_cf[4];
    float Q[6][4];
#pragma unroll
    for (int k = 0; k < 6; k++)
#pragma unroll
        for (int j = 0; j < 4; j++) Q[k][j] = d_Q[k][j];

    const float* xrow = x + (size_t)row_id * TLEN;
    float* yrow = out + (size_t)row_id * TLEN;

    unsigned int sb0 = (unsigned int)__cvta_generic_to_shared(buf0);
    unsigned int sb1 = (unsigned int)__cvta_generic_to_shared(buf1);

    if (tid == 0) { carry[0] = 0.0f; carry[1] = 0.0f; }

    // prefetch chunk 0
    load_chunk(xrow, sb0, w, l);

#pragma unroll
    for (int c = 0; c < NCHUNK; c++) {
        float* b = (c & 1) ? buf1 : buf0;
        if (c + 1 < NCHUNK) {
            load_chunk(xrow + (c + 1) * CHUNK, ((c + 1) & 1) ? sb1 : sb0, w, l);
            asm volatile("cp.async.wait_group 1;\n");
        } else {
            asm volatile("cp.async.wait_group 0;\n");
        }
        __syncthreads();   // chunk c resident for all threads (also covers carry init)

        // ---- pass 1: zero-state sub-block -> v ----
        float* r = b + tid * RSTR;
        float z1 = 0.0f, z2 = 0.0f, yv;
#pragma unroll
        for (int k = 0; k < LSUB; k++) {
            dsvf_step(r[k], b0, b1, b2, na1, na2, z1, z2, yv);
        }
        const float v1 = z1, v2 = z2;

        // ---- scan #1: intra-warp totals ----
        float s1 = v1, s2 = v2;
        warp_scan(s1, s2, Q, l);
        if (l == 31) { warpsum[2 * w] = s1; warpsum[2 * w + 1] = s2; }
        __syncthreads();

        // ---- serial cross-warp scan (thread 0) ----
        if (tid == 0) {
            float t1 = carry[0], t2 = carry[1];
#pragma unroll
            for (int u = 0; u < 8; u++) {
                entry[2 * u] = t1; entry[2 * u + 1] = t2;
                float w1 = warpsum[2 * u], w2 = warpsum[2 * u + 1];
                float n1 = fmaf(Q[5][0], t1, fmaf(Q[5][1], t2, w1));
                float n2 = fmaf(Q[5][2], t1, fmaf(Q[5][3], t2, w2));
                t1 = n1; t2 = n2;
            }
            carry[0] = t1; carry[1] = t2;
        }
        __syncthreads();

        // ---- scan #2 with warp-entry injected into lane 0 ----
        const float E1 = entry[2 * w], E2 = entry[2 * w + 1];
        s1 = v1; s2 = v2;
        if (l == 0) {
            s1 = fmaf(Q[0][0], E1, fmaf(Q[0][1], E2, s1));
            s2 = fmaf(Q[0][2], E1, fmaf(Q[0][3], E2, s2));
        }
        warp_scan(s1, s2, Q, l);
        float p1 = __shfl_up_sync(0xffffffffu, s1, 1);
        float p2 = __shfl_up_sync(0xffffffffu, s2, 1);
        if (l == 0) { p1 = E1; p2 = E2; }

        // ---- pass 2: true entry state, write y in place ----
        z1 = p1; z2 = p2;
#pragma unroll
        for (int k = 0; k < LSUB; k++) {
            float xv = r[k];
            dsvf_step(xv, b0, b1, b2, na1, na2, z1, z2, yv);
            r[k] = yv;
        }
        __syncthreads();   // all rows written before cross-thread store reads

        // ---- coalesced store (conflict-free scalar LDS -> STG.128) ----
        float* go = yrow + c * CHUNK;
#pragma unroll
        for (int i = 0; i < 8; i++) {
            int f = (w << 8) + (i << 5) + l;   // float4 index in chunk
            int e = f << 2;
            int rr = e >> 5, cc = e & 31;
            float4 o;
            o.x = b[rr * RSTR + cc + 0];
            o.y = b[rr * RSTR + cc + 1];
            o.z = b[rr * RSTR + cc + 2];
            o.w = b[rr * RSTR + cc + 3];
            reinterpret_cast<float4*>(go)[f] = o;
        }
        __syncthreads();   // buffer free before it is reloaded (chunk c+2)
    }
}

// ---------------------------------------------------------------------------
extern "C" void kernel_launch(void* const* d_in, const int* in_sizes, int n_in,
                              void* d_out, int out_size) {
    const float* x    = (const float*)d_in[0];
    const float* g    = (const float*)d_in[1];
    const float* r    = (const float*)d_in[2];
    const float* m_hp = (const float*)d_in[3];
    const float* m_bp = (const float*)d_in[4];
    const float* m_lp = (const float*)d_in[5];
    float* out = (float*)d_out;

    cudaFuncSetAttribute(dsvf_fused_kernel,
                         cudaFuncAttributeMaxDynamicSharedMemorySize, SMEM_BYTES);

    dsvf_coeffs_kernel<<<1, 1>>>(g, r, m_hp, m_bp, m_lp);
    dsvf_fused_kernel<<<BATCH, NTH, SMEM_BYTES>>>(x, out);
}

// round 6
// speedup vs baseline: 5.5869x; 1.0564x over previous
#include <cuda_runtime.h>
#include <stdint.h>
#include <math.h>

#define BATCH  512
#define TLEN   32768
#define NTH    256
#define CHUNK  4096                  // samples per chunk (16 KB)
#define NCHUNK (TLEN / CHUNK)        // 8
#define LSUB   (CHUNK / NTH)         // 16 samples per thread per chunk
#define RSTR   17                    // padded smem row stride (floats)
#define BUFSZ  (NTH * RSTR)          // 4352 floats per buffer
// extras: warpsum 16 + entry 16 + cf 8 + Q 32 = 72 floats
#define SMEM_FLOATS (2 * BUFSZ + 72)
#define SMEM_BYTES  (SMEM_FLOATS * 4)

// ---------------------------------------------------------------------------
// Helpers
// ---------------------------------------------------------------------------
__device__ __forceinline__ void dsvf_step(float x, float b0, float b1, float b2,
                                          float na1, float na2,
                                          float& z1, float& z2, float& y) {
    y = fmaf(b0, x, z1);
    z1 = fmaf(na1, y, fmaf(b1, x, z2));
    z2 = fmaf(na2, y, b2 * x);
}

__device__ __forceinline__ void cp_async4(unsigned int dst, const float* src) {
    asm volatile("cp.async.ca.shared.global [%0], [%1], 4;\n" ::
                 "r"(dst), "l"(src));
}

// stage one 4096-sample chunk into padded-transposed smem, coalesced
__device__ __forceinline__ void load_chunk(const float* __restrict__ g,
                                           unsigned int sbuf, int tid) {
#pragma unroll
    for (int i = 0; i < LSUB; i++) {
        int e = i * NTH + tid;                 // chunk-local element index
        int row = e >> 4, col = e & 15;        // row r = thread r's data
        cp_async4(sbuf + (unsigned int)(row * RSTR + col) * 4u, g + e);
    }
    asm volatile("cp.async.commit_group;\n");
}

// intra-warp inclusive matrix-monoid scan; Q matrices read from smem (broadcast)
__device__ __forceinline__ void warp_scan(float& s1, float& s2,
                                          const float* sQ, int l) {
#pragma unroll
    for (int d = 0; d < 5; d++) {
        int o = 1 << d;
        float q0 = sQ[4 * d + 0], q1 = sQ[4 * d + 1];
        float q2 = sQ[4 * d + 2], q3 = sQ[4 * d + 3];
        float u1 = __shfl_up_sync(0xffffffffu, s1, o);
        float u2 = __shfl_up_sync(0xffffffffu, s2, o);
        if (l >= o) {
            s1 = fmaf(q0, u1, fmaf(q1, u2, s1));
            s2 = fmaf(q2, u1, fmaf(q3, u2, s2));
        }
    }
}

// ---------------------------------------------------------------------------
// Single fused kernel: one CTA per row, 8 double-buffered chunks,
// coeffs + scan matrices computed per-CTA (overlapped with chunk-0 prefetch)
// ---------------------------------------------------------------------------
__global__ void __launch_bounds__(NTH, 4)
dsvf_fused_kernel(const float* __restrict__ x, float* __restrict__ out,
                  const float* __restrict__ g_raw, const float* __restrict__ r_raw,
                  const float* __restrict__ m_hp, const float* __restrict__ m_bp,
                  const float* __restrict__ m_lp) {
    extern __shared__ float sm[];
    float* buf0    = sm;
    float* buf1    = sm + BUFSZ;
    float* warpsum = sm + 2 * BUFSZ;   // 16 floats
    float* entry   = warpsum + 16;     // 16 floats
    float* scf     = entry + 16;       // 8 floats (5 used)
    float* sQ      = scf + 8;          // 32 floats: Q[k] = A^(16*2^k), k=0..7

    const int tid = threadIdx.x;
    const int w = tid >> 5, l = tid & 31;

    const float* xrow = x + (size_t)blockIdx.x * TLEN;
    float* yrow = out + (size_t)blockIdx.x * TLEN;

    unsigned int sb0 = (unsigned int)__cvta_generic_to_shared(buf0);
    unsigned int sb1 = (unsigned int)__cvta_generic_to_shared(buf1);

    // prefetch chunk 0 first so coeff math overlaps the loads
    load_chunk(xrow, sb0, tid);

    if (tid == 0) {
        float sg = 1.0f / (1.0f + expf(-g_raw[0]));
        float gg = tanf(3.14159265358979323846f * sg * 0.5f);
        float rr = log1pf(expf(r_raw[0]));
        float g2 = gg * gg;
        float hp = m_hp[0], bp = m_bp[0], lp = m_lp[0];

        float b0 = g2 * lp + gg * bp + hp;
        float b1 = 2.0f * g2 * lp - 2.0f * hp;
        float b2 = g2 * lp - gg * bp + hp;
        float a0 = g2 + 2.0f * rr * gg + 1.0f;
        float a1 = 2.0f * g2 - 2.0f;
        float a2 = g2 - 2.0f * rr * gg + 1.0f;
        float inv = 1.0f / a0;
        b0 *= inv; b1 *= inv; b2 *= inv; a1 *= inv; a2 *= inv;
        scf[0] = b0; scf[1] = b1; scf[2] = b2; scf[3] = a1; scf[4] = a2;

        // A = [[-a1, 1], [-a2, 0]]; Q[k] = A^(16*2^k)
        double m00 = -(double)a1, m01 = 1.0, m10 = -(double)a2, m11 = 0.0;
#pragma unroll
        for (int i = 0; i < 4; i++) {     // A -> A^16
            double t00 = m00 * m00 + m01 * m10;
            double t01 = m00 * m01 + m01 * m11;
            double t10 = m10 * m00 + m11 * m10;
            double t11 = m10 * m01 + m11 * m11;
            m00 = t00; m01 = t01; m10 = t10; m11 = t11;
        }
        sQ[0] = (float)m00; sQ[1] = (float)m01;
        sQ[2] = (float)m10; sQ[3] = (float)m11;
#pragma unroll
        for (int k = 1; k < 8; k++) {
            double t00 = m00 * m00 + m01 * m10;
            double t01 = m00 * m01 + m01 * m11;
            double t10 = m10 * m00 + m11 * m10;
            double t11 = m10 * m01 + m11 * m11;
            m00 = t00; m01 = t01; m10 = t10; m11 = t11;
            sQ[4 * k + 0] = (float)m00; sQ[4 * k + 1] = (float)m01;
            sQ[4 * k + 2] = (float)m10; sQ[4 * k + 3] = (float)m11;
        }
    }

    float b0 = 0.f, b1 = 0.f, b2 = 0.f, na1 = 0.f, na2 = 0.f;
    float c1 = 0.f, c2 = 0.f;   // chunk carry state, live in warp 0's registers

#pragma unroll
    for (int c = 0; c < NCHUNK; c++) {
        float* b = (c & 1) ? buf1 : buf0;
        if (c + 1 < NCHUNK) {
            load_chunk(xrow + (c + 1) * CHUNK, ((c + 1) & 1) ? sb1 : sb0, tid);
            asm volatile("cp.async.wait_group 1;\n");
        } else {
            asm volatile("cp.async.wait_group 0;\n");
        }
        __syncthreads();   // chunk c resident; (c==0) also publishes coeffs/Q

        if (c == 0) {
            b0 = scf[0]; b1 = scf[1]; b2 = scf[2];
            na1 = -scf[3]; na2 = -scf[4];
        }

        // ---- pass 1: zero-state sub-block -> v ----
        float* r = b + tid * RSTR;
        float z1 = 0.0f, z2 = 0.0f, yv;
#pragma unroll
        for (int k = 0; k < LSUB; k++)
            dsvf_step(r[k], b0, b1, b2, na1, na2, z1, z2, yv);
        const float v1 = z1, v2 = z2;

        // ---- scan #1: intra-warp inclusive ----
        float s1 = v1, s2 = v2;
        warp_scan(s1, s2, sQ, l);
        if (l == 31) { warpsum[2 * w] = s1; warpsum[2 * w + 1] = s2; }
        __syncthreads();

        // ---- cross-warp scan (warp 0, 8 elements, Kogge-Stone with carry) ----
        if (w == 0) {
            float t1 = 0.f, t2 = 0.f;
            if (l < 8) { t1 = warpsum[2 * l]; t2 = warpsum[2 * l + 1]; }
            if (l == 0) {   // inject carry: t0 = Q5*carry + t0   (Q5 = A^512)
                t1 = fmaf(sQ[20], c1, fmaf(sQ[21], c2, t1));
                t2 = fmaf(sQ[22], c1, fmaf(sQ[23], c2, t2));
            }
#pragma unroll
            for (int d = 0; d < 3; d++) {   // levels use Q[5+d] = A^(512*2^d)
                int o = 1 << d;
                float q0 = sQ[4 * (5 + d) + 0], q1 = sQ[4 * (5 + d) + 1];
                float q2 = sQ[4 * (5 + d) + 2], q3 = sQ[4 * (5 + d) + 3];
                float u1 = __shfl_up_sync(0xffffffffu, t1, o);
                float u2 = __shfl_up_sync(0xffffffffu, t2, o);
                if (l >= o && l < 8) {
                    t1 = fmaf(q0, u1, fmaf(q1, u2, t1));
                    t2 = fmaf(q2, u1, fmaf(q3, u2, t2));
                }
            }
            float p1 = __shfl_up_sync(0xffffffffu, t1, 1);
            float p2 = __shfl_up_sync(0xffffffffu, t2, 1);
            if (l == 0) { p1 = c1; p2 = c2; }
            if (l < 8) { entry[2 * l] = p1; entry[2 * l + 1] = p2; }
            // new carry = inclusive state of warp 7, broadcast to all lanes
            c1 = __shfl_sync(0xffffffffu, t1, 7);
            c2 = __shfl_sync(0xffffffffu, t2, 7);
        }
        __syncthreads();

        // ---- scan #2: per-thread entry state with warp-entry injection ----
        const float E1 = entry[2 * w], E2 = entry[2 * w + 1];
        s1 = v1; s2 = v2;
        if (l == 0) {   // s0 = Q0*E + v0   (Q0 = A^16)
            s1 = fmaf(sQ[0], E1, fmaf(sQ[1], E2, s1));
            s2 = fmaf(sQ[2], E1, fmaf(sQ[3], E2, s2));
        }
        warp_scan(s1, s2, sQ, l);
        float p1 = __shfl_up_sync(0xffffffffu, s1, 1);
        float p2 = __shfl_up_sync(0xffffffffu, s2, 1);
        if (l == 0) { p1 = E1; p2 = E2; }

        // ---- pass 2: true entry state, write y in place ----
        z1 = p1; z2 = p2;
#pragma unroll
        for (int k = 0; k < LSUB; k++) {
            float xv = r[k];
            dsvf_step(xv, b0, b1, b2, na1, na2, z1, z2, yv);
            r[k] = yv;
        }
        __syncthreads();   // all rows written before cross-thread store reads

        // ---- coalesced store (scalar LDS -> STG.128) ----
        float* go = yrow + c * CHUNK;
#pragma unroll
        for (int i = 0; i < 4; i++) {
            int f = i * NTH + tid;          // float4 index within chunk
            int rr = f >> 2, cc = (f & 3) << 2;
            float4 o;
            o.x = b[rr * RSTR + cc + 0];
            o.y = b[rr * RSTR + cc + 1];
            o.z = b[rr * RSTR + cc + 2];
            o.w = b[rr * RSTR + cc + 3];
            reinterpret_cast<float4*>(go)[f] = o;
        }
        __syncthreads();   // buffer free before it is refilled (chunk c+2)
    }
}

// ---------------------------------------------------------------------------
extern "C" void kernel_launch(void* const* d_in, const int* in_sizes, int n_in,
                              void* d_out, int out_size) {
    const float* x    = (const float*)d_in[0];
    const float* g    = (const float*)d_in[1];
    const float* r    = (const float*)d_in[2];
    const float* m_hp = (const float*)d_in[3];
    const float* m_bp = (const float*)d_in[4];
    const float* m_lp = (const float*)d_in[5];
    float* out = (float*)d_out;

    cudaFuncSetAttribute(dsvf_fused_kernel,
                         cudaFuncAttributeMaxDynamicSharedMemorySize, SMEM_BYTES);

    dsvf_fused_kernel<<<BATCH, NTH, SMEM_BYTES>>>(x, out, g, r, m_hp, m_bp, m_lp);
}

// round 7
// speedup vs baseline: 6.1997x; 1.1097x over previous
#include <cuda_runtime.h>
#include <stdint.h>
#include <math.h>

#define BATCH  512
#define TLEN   32768
#define NTH    256
#define CHUNK  4096                  // samples per chunk (16 KB)
#define NCHUNK (TLEN / CHUNK)        // 8
#define LSUB   16                    // samples per thread per chunk
#define NBUF   3                     // triple buffer -> depth-2 prefetch
#define BUFSZ  (NTH * 16)            // 4096 floats (swizzled, no pad)
// extras: warpsum 16 + scf 8 + sQ 32 = 56 floats
#define SMEM_FLOATS (NBUF * BUFSZ + 56)
#define SMEM_BYTES  (SMEM_FLOATS * 4)

// ---------------------------------------------------------------------------
__device__ __forceinline__ void dsvf_step(float x, float b0, float b1, float b2,
                                          float na1, float na2,
                                          float& z1, float& z2, float& y) {
    y = fmaf(b0, x, z1);
    z1 = fmaf(na1, y, fmaf(b1, x, z2));
    z2 = fmaf(na2, y, b2 * x);
}

__device__ __forceinline__ void cp_async16(unsigned int dst, const float* src) {
    asm volatile("cp.async.cg.shared.global [%0], [%1], 16;\n" ::
                 "r"(dst), "l"(src));
}

// stage one chunk into swizzled-transposed smem: element e -> row e>>4,
// float4-group (e>>2)&3 XOR'd with (row>>1)&3 (conflict-free .128 access)
__device__ __forceinline__ void load_chunk(const float* __restrict__ g,
                                           unsigned int sbuf, int tid) {
#pragma unroll
    for (int i = 0; i < 4; i++) {
        int f = i * NTH + tid;                    // float4 index in chunk
        int rr = f >> 2, cc = f & 3;
        unsigned int off = (unsigned int)((rr * 16 + ((cc ^ ((rr >> 1) & 3)) << 2)) * 4);
        cp_async16(sbuf + off, g + f * 4);
    }
    asm volatile("cp.async.commit_group;\n");
}

// intra-warp inclusive matrix-monoid scan (Q from smem, broadcast)
__device__ __forceinline__ void warp_scan(float& s1, float& s2,
                                          const float* sQ, int l) {
#pragma unroll
    for (int d = 0; d < 5; d++) {
        int o = 1 << d;
        float q0 = sQ[4 * d + 0], q1 = sQ[4 * d + 1];
        float q2 = sQ[4 * d + 2], q3 = sQ[4 * d + 3];
        float u1 = __shfl_up_sync(0xffffffffu, s1, o);
        float u2 = __shfl_up_sync(0xffffffffu, s2, o);
        if (l >= o) {
            s1 = fmaf(q0, u1, fmaf(q1, u2, s1));
            s2 = fmaf(q2, u1, fmaf(q3, u2, s2));
        }
    }
}

// ---------------------------------------------------------------------------
__global__ void __launch_bounds__(NTH, 4)
dsvf_fused_kernel(const float* __restrict__ x, float* __restrict__ out,
                  const float* __restrict__ g_raw, const float* __restrict__ r_raw,
                  const float* __restrict__ m_hp, const float* __restrict__ m_bp,
                  const float* __restrict__ m_lp) {
    extern __shared__ float sm[];
    float* warpsum = sm + NBUF * BUFSZ;   // 16 floats
    float* scf     = warpsum + 16;        // 8 floats (5 used)
    float* sQ      = scf + 8;             // 32 floats: Q[k] = A^(16*2^k), k=0..7

    const int tid = threadIdx.x;
    const int w = tid >> 5, l = tid & 31;
    const int sw = (tid >> 1) & 3;        // this thread's row swizzle

    const float* xrow = x + (size_t)blockIdx.x * TLEN;
    float* yrow = out + (size_t)blockIdx.x * TLEN;

    unsigned int sb[NBUF];
#pragma unroll
    for (int i = 0; i < NBUF; i++)
        sb[i] = (unsigned int)__cvta_generic_to_shared(sm + i * BUFSZ);

    // prefetch chunks 0,1,2 (depth 3 initially) so coeff math overlaps
    load_chunk(xrow,             sb[0], tid);
    load_chunk(xrow + CHUNK,     sb[1], tid);
    load_chunk(xrow + 2 * CHUNK, sb[2], tid);

    if (tid == 0) {
        float sg = 1.0f / (1.0f + expf(-g_raw[0]));
        float gg = tanf(3.14159265358979323846f * sg * 0.5f);
        float rr = log1pf(expf(r_raw[0]));
        float g2 = gg * gg;
        float hp = m_hp[0], bp = m_bp[0], lp = m_lp[0];

        float b0 = g2 * lp + gg * bp + hp;
        float b1 = 2.0f * g2 * lp - 2.0f * hp;
        float b2 = g2 * lp - gg * bp + hp;
        float a0 = g2 + 2.0f * rr * gg + 1.0f;
        float a1 = 2.0f * g2 - 2.0f;
        float a2 = g2 - 2.0f * rr * gg + 1.0f;
        float inv = 1.0f / a0;
        b0 *= inv; b1 *= inv; b2 *= inv; a1 *= inv; a2 *= inv;
        scf[0] = b0; scf[1] = b1; scf[2] = b2; scf[3] = a1; scf[4] = a2;

        // A = [[-a1,1],[-a2,0]];  Q[k] = A^(16*2^k), k = 0..7
        double m00 = -(double)a1, m01 = 1.0, m10 = -(double)a2, m11 = 0.0;
#pragma unroll
        for (int i = 0; i < 4; i++) {   // A -> A^16
            double t00 = m00 * m00 + m01 * m10, t01 = m00 * m01 + m01 * m11;
            double t10 = m10 * m00 + m11 * m10, t11 = m10 * m01 + m11 * m11;
            m00 = t00; m01 = t01; m10 = t10; m11 = t11;
        }
        sQ[0] = (float)m00; sQ[1] = (float)m01; sQ[2] = (float)m10; sQ[3] = (float)m11;
#pragma unroll
        for (int k = 1; k < 8; k++) {
            double t00 = m00 * m00 + m01 * m10, t01 = m00 * m01 + m01 * m11;
            double t10 = m10 * m00 + m11 * m10, t11 = m10 * m01 + m11 * m11;
            m00 = t00; m01 = t01; m10 = t10; m11 = t11;
            sQ[4 * k + 0] = (float)m00; sQ[4 * k + 1] = (float)m01;
            sQ[4 * k + 2] = (float)m10; sQ[4 * k + 3] = (float)m11;
        }
    }
    __syncthreads();   // scf/sQ published (prefetches still in flight)

    const float b0 = scf[0], b1 = scf[1], b2 = scf[2];
    const float na1 = -scf[3], na2 = -scf[4];

    // ---- per-lane matrix P = A^(16*l)  (exclusive product scan; powers commute)
    float P00 = sQ[0], P01 = sQ[1], P10 = sQ[2], P11 = sQ[3];   // A^16
#pragma unroll
    for (int d = 0; d < 5; d++) {
        int o = 1 << d;
        float u00 = __shfl_up_sync(0xffffffffu, P00, o);
        float u01 = __shfl_up_sync(0xffffffffu, P01, o);
        float u10 = __shfl_up_sync(0xffffffffu, P10, o);
        float u11 = __shfl_up_sync(0xffffffffu, P11, o);
        if (l >= o) {
            float n00 = P00 * u00 + P01 * u10, n01 = P00 * u01 + P01 * u11;
            float n10 = P10 * u00 + P11 * u10, n11 = P10 * u01 + P11 * u11;
            P00 = n00; P01 = n01; P10 = n10; P11 = n11;
        }
    }
    {   // exclusive: shift up one lane, lane 0 = identity
        float e00 = __shfl_up_sync(0xffffffffu, P00, 1);
        float e01 = __shfl_up_sync(0xffffffffu, P01, 1);
        float e10 = __shfl_up_sync(0xffffffffu, P10, 1);
        float e11 = __shfl_up_sync(0xffffffffu, P11, 1);
        if (l == 0) { e00 = 1.f; e01 = 0.f; e10 = 0.f; e11 = 1.f; }
        P00 = e00; P01 = e01; P10 = e10; P11 = e11;
    }

    float c1 = 0.f, c2 = 0.f;   // chunk carry (identical in every thread)

#pragma unroll
    for (int c = 0; c < NCHUNK; c++) {
        float* b = sm + (c % NBUF) * BUFSZ;
        if (c < NCHUNK - 2)      asm volatile("cp.async.wait_group 2;\n");
        else if (c == NCHUNK - 2) asm volatile("cp.async.wait_group 1;\n");
        else                      asm volatile("cp.async.wait_group 0;\n");
        __syncthreads();   // chunk c resident for all threads

        // ---- pass 1: zero-state sub-block -> v ----
        const float4* rp = reinterpret_cast<const float4*>(b + tid * 16);
        float z1 = 0.f, z2 = 0.f, yv;
#pragma unroll
        for (int k = 0; k < 4; k++) {
            float4 xv = rp[k ^ sw];
            dsvf_step(xv.x, b0, b1, b2, na1, na2, z1, z2, yv);
            dsvf_step(xv.y, b0, b1, b2, na1, na2, z1, z2, yv);
            dsvf_step(xv.z, b0, b1, b2, na1, na2, z1, z2, yv);
            dsvf_step(xv.w, b0, b1, b2, na1, na2, z1, z2, yv);
        }

        // ---- scan #1: intra-warp inclusive (zero entry) ----
        float s1 = z1, s2 = z2;
        warp_scan(s1, s2, sQ, l);
        if (l == 31) { warpsum[2 * w] = s1; warpsum[2 * w + 1] = s2; }
        __syncthreads();

        // ---- cross-warp scan, redundantly in EVERY warp (lanes 0..7) ----
        float t1 = 0.f, t2 = 0.f;
        if (l < 8) { t1 = warpsum[2 * l]; t2 = warpsum[2 * l + 1]; }
        if (l == 0) {   // fold carry: t0 = Q5*c + t0  (Q5 = A^512)
            t1 = fmaf(sQ[20], c1, fmaf(sQ[21], c2, t1));
            t2 = fmaf(sQ[22], c1, fmaf(sQ[23], c2, t2));
        }
#pragma unroll
        for (int d = 0; d < 3; d++) {   // levels use Q[5+d] = A^(512*2^d)
            int o = 1 << d;
            float q0 = sQ[4 * (5 + d) + 0], q1 = sQ[4 * (5 + d) + 1];
            float q2 = sQ[4 * (5 + d) + 2], q3 = sQ[4 * (5 + d) + 3];
            float u1 = __shfl_up_sync(0xffffffffu, t1, o);
            float u2 = __shfl_up_sync(0xffffffffu, t2, o);
            if (l >= o && l < 8) {
                t1 = fmaf(q0, u1, fmaf(q1, u2, t1));
                t2 = fmaf(q2, u1, fmaf(q3, u2, t2));
            }
        }
        // warp entry E = inclusive total of warp w-1 (carry for w==0)
        float E1 = __shfl_sync(0xffffffffu, t1, (w > 0) ? (w - 1) : 0);
        float E2 = __shfl_sync(0xffffffffu, t2, (w > 0) ? (w - 1) : 0);
        if (w == 0) { E1 = c1; E2 = c2; }
        // next chunk's carry = inclusive total of warp 7
        c1 = __shfl_sync(0xffffffffu, t1, 7);
        c2 = __shfl_sync(0xffffffffu, t2, 7);

        // ---- thread entry = s_{l-1} + P_l * E  (no second warp scan) ----
        float p1 = __shfl_up_sync(0xffffffffu, s1, 1);
        float p2 = __shfl_up_sync(0xffffffffu, s2, 1);
        if (l == 0) { p1 = 0.f; p2 = 0.f; }
        z1 = fmaf(P00, E1, fmaf(P01, E2, p1));
        z2 = fmaf(P10, E1, fmaf(P11, E2, p2));

        // ---- pass 2: filter with true entry state, write y in place ----
        float4* wp = reinterpret_cast<float4*>(b + tid * 16);
#pragma unroll
        for (int k = 0; k < 4; k++) {
            float4 xv = rp[k ^ sw];
            float4 o;
            dsvf_step(xv.x, b0, b1, b2, na1, na2, z1, z2, o.x);
            dsvf_step(xv.y, b0, b1, b2, na1, na2, z1, z2, o.y);
            dsvf_step(xv.z, b0, b1, b2, na1, na2, z1, z2, o.z);
            dsvf_step(xv.w, b0, b1, b2, na1, na2, z1, z2, o.w);
            wp[k ^ sw] = o;
        }
        __syncthreads();   // all rows written before cross-thread store reads

        // ---- coalesced store (swizzled LDS.128 -> STG.128) ----
        float4* go4 = reinterpret_cast<float4*>(yrow + c * CHUNK);
#pragma unroll
        for (int i = 0; i < 4; i++) {
            int f = i * NTH + tid;
            int rr = f >> 2, cc = f & 3;
            float4 o = reinterpret_cast<const float4*>(b + rr * 16)[cc ^ ((rr >> 1) & 3)];
            go4[f] = o;
        }
        __syncthreads();   // buffer drained before refill below

        if (c + NBUF < NCHUNK)
            load_chunk(xrow + (c + NBUF) * CHUNK, sb[(c + NBUF) % NBUF], tid);
    }
}

// ---------------------------------------------------------------------------
extern "C" void kernel_launch(void* const* d_in, const int* in_sizes, int n_in,
                              void* d_out, int out_size) {
    const float* x    = (const float*)d_in[0];
    const float* g    = (const float*)d_in[1];
    const float* r    = (const float*)d_in[2];
    const float* m_hp = (const float*)d_in[3];
    const float* m_bp = (const float*)d_in[4];
    const float* m_lp = (const float*)d_in[5];
    float* out = (float*)d_out;

    cudaFuncSetAttribute(dsvf_fused_kernel,
                         cudaFuncAttributeMaxDynamicSharedMemorySize, SMEM_BYTES);

    dsvf_fused_kernel<<<BATCH, NTH, SMEM_BYTES>>>(x, out, g, r, m_hp, m_bp, m_lp);
}